// round 1
// baseline (speedup 1.0000x reference)
#include <cuda_runtime.h>

// Problem constants (fixed by the dataset)
#define BB 4
#define LQ 4096
#define LK 5119
#define DD 512
#define CACHE_LEN 1024
#define EPSV 1e-5f

#define TSZ 256
#define NT ((LK + TSZ - 1) / TSZ)   // 20 tiles

// ---------------- scratch (__device__ globals; no allocations allowed) -----
__device__ float2 g_st_q[BB * LQ];
__device__ float2 g_st_k[BB * LK];
__device__ float2 g_st_v[BB * LK];
__device__ float  g_rq[(size_t)BB * LQ * DD];        // relu(qp)
__device__ float  g_rk[(size_t)BB * LK * DD];        // relu(kp)
__device__ float  g_vp[(size_t)BB * LK * DD];        // vp
__device__ float  g_kv[(size_t)BB * LK * DD];        // relu(kp)*vp
__device__ float  g_cs[(size_t)BB * (LK + 1) * DD];  // exclusive prefix sums
__device__ float  g_tile[BB * NT * DD];              // tile partial sums

// ---------------- per-row LayerNorm stats (mean, rstd) ---------------------
__global__ void rowstats_kernel(const float* __restrict__ x,
                                float2* __restrict__ st, int nrows) {
    int row = blockIdx.x;
    if (row >= nrows) return;
    const float4* xr = reinterpret_cast<const float4*>(x) + (size_t)row * (DD / 4);
    float s = 0.f, s2 = 0.f;
    for (int i = threadIdx.x; i < DD / 4; i += blockDim.x) {
        float4 v = xr[i];
        s  += v.x + v.y + v.z + v.w;
        s2 += v.x * v.x + v.y * v.y + v.z * v.z + v.w * v.w;
    }
    #pragma unroll
    for (int o = 16; o > 0; o >>= 1) {
        s  += __shfl_down_sync(0xffffffffu, s, o);
        s2 += __shfl_down_sync(0xffffffffu, s2, o);
    }
    __shared__ float ss[4], ss2[4];
    int w = threadIdx.x >> 5, lane = threadIdx.x & 31;
    if (lane == 0) { ss[w] = s; ss2[w] = s2; }
    __syncthreads();
    if (threadIdx.x == 0) {
        float S = 0.f, S2 = 0.f;
        int nw = blockDim.x >> 5;
        for (int i = 0; i < nw; i++) { S += ss[i]; S2 += ss2[i]; }
        float m   = S / (float)DD;
        float var = S2 / (float)DD - m * m;
        st[row] = make_float2(m, rsqrtf(var + EPSV));
    }
}

// ---------------- LN-fused fp32 GEMM: C = [relu](LN(A) @ W + bw) -----------
#define BM 128
#define BN 128
#define BK 16

__global__ __launch_bounds__(256)
void ln_gemm_kernel(const float* __restrict__ A, const float2* __restrict__ st,
                    const float* __restrict__ gam, const float* __restrict__ bet,
                    const float* __restrict__ W, const float* __restrict__ bw,
                    float* __restrict__ C, int M, int do_relu) {
    __shared__ float As[BK][BM];
    __shared__ float Bs[BK][BN];
    __shared__ float gs[DD];
    __shared__ float bs[DD];

    int tid = threadIdx.x;
    int bm = blockIdx.y * BM;
    int bn = blockIdx.x * BN;

    for (int i = tid; i < DD; i += 256) { gs[i] = gam[i]; bs[i] = bet[i]; }

    // A-tile load mapping: 2 float4 per thread
    int arow = tid >> 2;            // 0..63
    int acol = (tid & 3) << 2;      // 0,4,8,12
    int gm0 = bm + arow;
    int gm1 = bm + arow + 64;
    float2 s0 = (gm0 < M) ? st[gm0] : make_float2(0.f, 1.f);
    float2 s1 = (gm1 < M) ? st[gm1] : make_float2(0.f, 1.f);

    // B-tile load mapping: 2 float4 per thread
    int brow = tid >> 5;            // 0..7
    int bcol = (tid & 31) << 2;

    // compute tile mapping: 16x16 threads, 8x8 each
    int ty = tid >> 4, tx = tid & 15;
    int tm = ty << 3, tn = tx << 3;

    float acc[8][8];
    #pragma unroll
    for (int i = 0; i < 8; i++)
        #pragma unroll
        for (int j = 0; j < 8; j++) acc[i][j] = 0.f;

    __syncthreads();  // gs/bs ready

    for (int k0 = 0; k0 < DD; k0 += BK) {
        float4 a0 = (gm0 < M) ? *(const float4*)(A + (size_t)gm0 * DD + k0 + acol)
                              : make_float4(0.f, 0.f, 0.f, 0.f);
        float4 a1 = (gm1 < M) ? *(const float4*)(A + (size_t)gm1 * DD + k0 + acol)
                              : make_float4(0.f, 0.f, 0.f, 0.f);
        float g0 = gs[k0 + acol + 0], g1 = gs[k0 + acol + 1];
        float g2 = gs[k0 + acol + 2], g3 = gs[k0 + acol + 3];
        float e0 = bs[k0 + acol + 0], e1 = bs[k0 + acol + 1];
        float e2 = bs[k0 + acol + 2], e3 = bs[k0 + acol + 3];

        As[acol + 0][arow] = (a0.x - s0.x) * s0.y * g0 + e0;
        As[acol + 1][arow] = (a0.y - s0.x) * s0.y * g1 + e1;
        As[acol + 2][arow] = (a0.z - s0.x) * s0.y * g2 + e2;
        As[acol + 3][arow] = (a0.w - s0.x) * s0.y * g3 + e3;
        As[acol + 0][arow + 64] = (a1.x - s1.x) * s1.y * g0 + e0;
        As[acol + 1][arow + 64] = (a1.y - s1.x) * s1.y * g1 + e1;
        As[acol + 2][arow + 64] = (a1.z - s1.x) * s1.y * g2 + e2;
        As[acol + 3][arow + 64] = (a1.w - s1.x) * s1.y * g3 + e3;

        float4 b0 = *(const float4*)(W + (size_t)(k0 + brow) * DD + bn + bcol);
        float4 b1 = *(const float4*)(W + (size_t)(k0 + brow + 8) * DD + bn + bcol);
        *(float4*)&Bs[brow][bcol]     = b0;
        *(float4*)&Bs[brow + 8][bcol] = b1;

        __syncthreads();

        #pragma unroll
        for (int k = 0; k < BK; k++) {
            float4 a04 = *(const float4*)&As[k][tm];
            float4 a14 = *(const float4*)&As[k][tm + 4];
            float4 b04 = *(const float4*)&Bs[k][tn];
            float4 b14 = *(const float4*)&Bs[k][tn + 4];
            float av[8] = {a04.x, a04.y, a04.z, a04.w, a14.x, a14.y, a14.z, a14.w};
            float bv[8] = {b04.x, b04.y, b04.z, b04.w, b14.x, b14.y, b14.z, b14.w};
            #pragma unroll
            for (int i = 0; i < 8; i++)
                #pragma unroll
                for (int j = 0; j < 8; j++)
                    acc[i][j] += av[i] * bv[j];
        }
        __syncthreads();
    }

    #pragma unroll
    for (int i = 0; i < 8; i++) {
        int gm = bm + tm + i;
        if (gm < M) {
            float4 o0, o1;
            o0.x = acc[i][0] + bw[bn + tn + 0];
            o0.y = acc[i][1] + bw[bn + tn + 1];
            o0.z = acc[i][2] + bw[bn + tn + 2];
            o0.w = acc[i][3] + bw[bn + tn + 3];
            o1.x = acc[i][4] + bw[bn + tn + 4];
            o1.y = acc[i][5] + bw[bn + tn + 5];
            o1.z = acc[i][6] + bw[bn + tn + 6];
            o1.w = acc[i][7] + bw[bn + tn + 7];
            if (do_relu) {
                o0.x = fmaxf(o0.x, 0.f); o0.y = fmaxf(o0.y, 0.f);
                o0.z = fmaxf(o0.z, 0.f); o0.w = fmaxf(o0.w, 0.f);
                o1.x = fmaxf(o1.x, 0.f); o1.y = fmaxf(o1.y, 0.f);
                o1.z = fmaxf(o1.z, 0.f); o1.w = fmaxf(o1.w, 0.f);
            }
            *(float4*)(C + (size_t)gm * DD + bn + tn)     = o0;
            *(float4*)(C + (size_t)gm * DD + bn + tn + 4) = o1;
        }
    }
}

// ---------------- kv = relu(kp)*vp, plus per-tile partial sums -------------
__global__ void kv_tilesum_kernel() {
    int t = blockIdx.x, dc = blockIdx.y, b = blockIdx.z;
    int d = dc * 128 + threadIdx.x;
    float sum = 0.f;
    size_t base = ((size_t)b * LK) * DD + d;
    for (int r = 0; r < TSZ; r++) {
        int l = t * TSZ + r;
        if (l < LK) {
            size_t idx = base + (size_t)l * DD;
            float kvv = g_rk[idx] * g_vp[idx];
            g_kv[idx] = kvv;
            sum += kvv;
        }
    }
    g_tile[(b * NT + t) * DD + d] = sum;
}

// ---------------- exclusive scan of tile sums (tiny) -----------------------
__global__ void tile_scan_kernel() {
    int d = blockIdx.x * 128 + threadIdx.x;
    int b = blockIdx.y;
    float run = 0.f;
    for (int t = 0; t < NT; t++) {
        int idx = (b * NT + t) * DD + d;
        float v = g_tile[idx];
        g_tile[idx] = run;
        run += v;
    }
}

// ---------------- full exclusive prefix sums cs ----------------------------
__global__ void cs_kernel() {
    int t = blockIdx.x, dc = blockIdx.y, b = blockIdx.z;
    int d = dc * 128 + threadIdx.x;
    float run = g_tile[(b * NT + t) * DD + d];
    size_t kvbase = ((size_t)b * LK) * DD + d;
    size_t csbase = ((size_t)b * (LK + 1)) * DD + d;
    for (int r = 0; r < TSZ; r++) {
        int l = t * TSZ + r;
        if (l < LK) {
            g_cs[csbase + (size_t)l * DD] = run;
            run += g_kv[kvbase + (size_t)l * DD];
        }
    }
    if (t == NT - 1) g_cs[csbase + (size_t)LK * DD] = run;
}

// ---------------- out = relu(qp) * (cs[start+W] - cs[start]) ---------------
__global__ void combine_kernel(float* __restrict__ out) {
    int e = blockIdx.x * blockDim.x + threadIdx.x;
    const int D4 = DD / 4;
    if (e >= BB * LQ * D4) return;
    int d4 = e % D4;
    int i  = (e / D4) % LQ;
    int b  = e / (D4 * LQ);
    const int sup = LK - LQ - CACHE_LEN + 1;
    int start = sup + i;
    const float4* cs = reinterpret_cast<const float4*>(g_cs);
    size_t cb = ((size_t)b * (LK + 1)) * D4 + d4;
    float4 c1 = cs[cb + (size_t)(start + CACHE_LEN) * D4];
    float4 c0 = cs[cb + (size_t)start * D4];
    float4 rq = reinterpret_cast<const float4*>(g_rq)[e];
    float4 o;
    o.x = rq.x * (c1.x - c0.x);
    o.y = rq.y * (c1.y - c0.y);
    o.z = rq.z * (c1.z - c0.z);
    o.w = rq.w * (c1.w - c0.w);
    reinterpret_cast<float4*>(out)[e] = o;
}

// ---------------------------------------------------------------------------
extern "C" void kernel_launch(void* const* d_in, const int* in_sizes, int n_in,
                              void* d_out, int out_size) {
    const float* q   = (const float*)d_in[0];
    const float* k   = (const float*)d_in[1];
    const float* v   = (const float*)d_in[2];
    const float* gq  = (const float*)d_in[3];
    const float* bq  = (const float*)d_in[4];
    const float* gk  = (const float*)d_in[5];
    const float* bk  = (const float*)d_in[6];
    const float* gv  = (const float*)d_in[7];
    const float* bv  = (const float*)d_in[8];
    const float* Wq  = (const float*)d_in[9];
    const float* bwq = (const float*)d_in[10];
    const float* Wk  = (const float*)d_in[11];
    const float* bwk = (const float*)d_in[12];
    const float* Wv  = (const float*)d_in[13];
    const float* bwv = (const float*)d_in[14];

    void *stq_, *stk_, *stv_, *rq_, *rk_, *vp_;
    cudaGetSymbolAddress(&stq_, g_st_q);
    cudaGetSymbolAddress(&stk_, g_st_k);
    cudaGetSymbolAddress(&stv_, g_st_v);
    cudaGetSymbolAddress(&rq_, g_rq);
    cudaGetSymbolAddress(&rk_, g_rk);
    cudaGetSymbolAddress(&vp_, g_vp);
    float2* stq = (float2*)stq_;
    float2* stk = (float2*)stk_;
    float2* stv = (float2*)stv_;
    float* rq = (float*)rq_;
    float* rk = (float*)rk_;
    float* vp = (float*)vp_;

    rowstats_kernel<<<BB * LQ, 128>>>(q, stq, BB * LQ);
    rowstats_kernel<<<BB * LK, 128>>>(k, stk, BB * LK);
    rowstats_kernel<<<BB * LK, 128>>>(v, stv, BB * LK);

    dim3 gqg(DD / BN, (BB * LQ + BM - 1) / BM);
    dim3 gkg(DD / BN, (BB * LK + BM - 1) / BM);
    ln_gemm_kernel<<<gqg, 256>>>(q, stq, gq, bq, Wq, bwq, rq, BB * LQ, 1);
    ln_gemm_kernel<<<gkg, 256>>>(k, stk, gk, bk, Wk, bwk, rk, BB * LK, 1);
    ln_gemm_kernel<<<gkg, 256>>>(v, stv, gv, bv, Wv, bwv, vp, BB * LK, 0);

    kv_tilesum_kernel<<<dim3(NT, DD / 128, BB), 128>>>();
    tile_scan_kernel<<<dim3(DD / 128, BB), 128>>>();
    cs_kernel<<<dim3(NT, DD / 128, BB), 128>>>();

    combine_kernel<<<(BB * LQ * (DD / 4) + 255) / 256, 256>>>((float*)d_out);
}

// round 3
// speedup vs baseline: 1.8466x; 1.8466x over previous
#include <cuda_runtime.h>
#include <cuda_bf16.h>
#include <cstdint>

// Problem constants (fixed by the dataset)
#define BB 4
#define LQ 4096
#define LK 5119
#define DD 512
#define CACHE_LEN 1024
#define EPSV 1e-5f

#define TSZ 64
#define NT ((LK + TSZ - 1) / TSZ)   // 80 tiles

// GEMM tiling
#define MT 128           // M rows per CTA
#define NTC 128          // N cols per CTA
#define KCH 64           // K chunk
#define ROWB 144         // padded row stride in bytes (72 bf16 = 64 + 8 pad)

// smem layout (bytes)
#define S_GAM   0
#define S_BET   2048
#define S_RAWA  4096                         // 128 x 64 fp32 = 32768
#define S_AH    (S_RAWA + 32768)             // 2 x 18432
#define S_AL    (S_AH + 2 * 18432)
#define S_BH    (S_AL + 2 * 18432)
#define S_BL    (S_BH + 2 * 18432)
#define S_TOTAL (S_BL + 2 * 18432)           // 184320

// ---------------- scratch (__device__ globals) -----------------------------
__device__ float2 g_st_q[BB * LQ];
__device__ float2 g_st_k[BB * LK];
__device__ float2 g_st_v[BB * LK];
__device__ float  g_rq[(size_t)BB * LQ * DD];        // relu(qp)
__device__ float  g_rk[(size_t)BB * LK * DD];        // relu(kp)
__device__ float  g_vp[(size_t)BB * LK * DD];        // vp
__device__ float  g_cs[(size_t)BB * (LK + 1) * DD];  // exclusive prefix sums
__device__ float  g_tile[BB * NT * DD];              // tile partial sums
__device__ __align__(256) __nv_bfloat16 g_wt[3 * 2 * DD * DD]; // [w][hi/lo][n][k]

// ================= helpers ================================================
__device__ __forceinline__ uint32_t smem_u32(const void* p) {
    uint32_t a;
    asm("{ .reg .u64 t; cvta.to.shared.u64 t, %1; cvt.u32.u64 %0, t; }" : "=r"(a) : "l"(p));
    return a;
}
__device__ __forceinline__ uint32_t lds32(uint32_t addr) {
    uint32_t v;
    asm volatile("ld.shared.b32 %0, [%1];" : "=r"(v) : "r"(addr));
    return v;
}
__device__ __forceinline__ void sts64(uint32_t addr, uint32_t x, uint32_t y) {
    asm volatile("st.shared.v2.b32 [%0], {%1, %2};" :: "r"(addr), "r"(x), "r"(y));
}
__device__ __forceinline__ void cp16(uint32_t dst, const void* src) {
    asm volatile("cp.async.cg.shared.global [%0], [%1], 16;" :: "r"(dst), "l"(src));
}
__device__ __forceinline__ void cp_commit() {
    asm volatile("cp.async.commit_group;");
}
__device__ __forceinline__ void cp_wait0() {
    asm volatile("cp.async.wait_group 0;");
}
__device__ __forceinline__ void mma16816(float* c, const uint32_t* a,
                                         uint32_t b0, uint32_t b1) {
    asm volatile(
        "mma.sync.aligned.m16n8k16.row.col.f32.bf16.bf16.f32 "
        "{%0,%1,%2,%3}, {%4,%5,%6,%7}, {%8,%9}, {%0,%1,%2,%3};"
        : "+f"(c[0]), "+f"(c[1]), "+f"(c[2]), "+f"(c[3])
        : "r"(a[0]), "r"(a[1]), "r"(a[2]), "r"(a[3]), "r"(b0), "r"(b1));
}

// ---------------- W prep: transpose + bf16 hi/lo split ---------------------
__global__ void wprep_kernel(const float* __restrict__ W0,
                             const float* __restrict__ W1,
                             const float* __restrict__ W2) {
    const float* W = (blockIdx.z == 0) ? W0 : (blockIdx.z == 1) ? W1 : W2;
    __shared__ float t[32][33];
    int n0 = blockIdx.x * 32, k0 = blockIdx.y * 32;
    int tx = threadIdx.x, ty = threadIdx.y;
    #pragma unroll
    for (int i = 0; i < 4; i++)
        t[ty + 8 * i][tx] = W[(size_t)(k0 + ty + 8 * i) * DD + n0 + tx];
    __syncthreads();
    __nv_bfloat16* hi = g_wt + (size_t)blockIdx.z * 2 * DD * DD;
    __nv_bfloat16* lo = hi + (size_t)DD * DD;
    #pragma unroll
    for (int i = 0; i < 4; i++) {
        int n = n0 + ty + 8 * i, k = k0 + tx;
        float v = t[tx][ty + 8 * i];
        __nv_bfloat16 h = __float2bfloat16(v);
        hi[(size_t)n * DD + k] = h;
        lo[(size_t)n * DD + k] = __float2bfloat16(v - __bfloat162float(h));
    }
}

// ---------------- per-row LayerNorm stats (mean, rstd) ---------------------
__global__ void rowstats_kernel(const float* __restrict__ x,
                                float2* __restrict__ st, int nrows) {
    int row = blockIdx.x;
    if (row >= nrows) return;
    const float4* xr = reinterpret_cast<const float4*>(x) + (size_t)row * (DD / 4);
    float s = 0.f, s2 = 0.f;
    for (int i = threadIdx.x; i < DD / 4; i += blockDim.x) {
        float4 v = xr[i];
        s  += v.x + v.y + v.z + v.w;
        s2 += v.x * v.x + v.y * v.y + v.z * v.z + v.w * v.w;
    }
    #pragma unroll
    for (int o = 16; o > 0; o >>= 1) {
        s  += __shfl_down_sync(0xffffffffu, s, o);
        s2 += __shfl_down_sync(0xffffffffu, s2, o);
    }
    __shared__ float ss[4], ss2[4];
    int w = threadIdx.x >> 5, lane = threadIdx.x & 31;
    if (lane == 0) { ss[w] = s; ss2[w] = s2; }
    __syncthreads();
    if (threadIdx.x == 0) {
        float S = 0.f, S2 = 0.f;
        int nw = blockDim.x >> 5;
        for (int i = 0; i < nw; i++) { S += ss[i]; S2 += ss2[i]; }
        float m   = S / (float)DD;
        float var = S2 / (float)DD - m * m;
        st[row] = make_float2(m, rsqrtf(var + EPSV));
    }
}

// ---------------- HMMA LN-fused GEMM ---------------------------------------
// C[m][n] = [relu]( LN(A)[m,:] @ W[:,n] + bw[n] ),  split-bf16 3-pass
__global__ __launch_bounds__(256, 1)
void gemm_mma_kernel(const float* __restrict__ A, const float2* __restrict__ st,
                     const float* __restrict__ gam, const float* __restrict__ bet,
                     const __nv_bfloat16* __restrict__ Wth,
                     const __nv_bfloat16* __restrict__ Wtl,
                     const float* __restrict__ bw, float* __restrict__ C,
                     int M, int do_relu) {
    extern __shared__ char smem[];
    const uint32_t su = smem_u32(smem);
    float* sG  = (float*)(smem + S_GAM);
    float* sB2 = (float*)(smem + S_BET);
    float* sRaw = (float*)(smem + S_RAWA);

    const int tid = threadIdx.x;
    const int wid = tid >> 5, lane = tid & 31;
    const int warpm = wid & 3, warpn = wid >> 2;
    const int g = lane >> 2, tig = lane & 3;
    const int bm = blockIdx.y * MT, bn = blockIdx.x * NTC;

    // gamma/beta to smem
    for (int i = tid; i < DD; i += 256) { sG[i] = gam[i]; sB2[i] = bet[i]; }

    // --- staging lambdas (as macros via plain code) ---
    // raw A chunk: 128 rows x 64 f32
    // B chunk: 128 n-rows x 64 k bf16, hi & lo

    float acc[2][8][4];
    #pragma unroll
    for (int mi = 0; mi < 2; mi++)
        #pragma unroll
        for (int ni = 0; ni < 8; ni++)
            #pragma unroll
            for (int r = 0; r < 4; r++) acc[mi][ni][r] = 0.f;

    // per-lane fragment base offsets (within one tile buffer)
    // A: row = warpm*32 + mi*16 + g, byte = row*ROWB + tig*4 (+ks*32, +16)
    const uint32_t aoff0 = (uint32_t)((warpm * 32 + g) * ROWB + tig * 4);
    // B: n = warpn*64 + ni*8 + g
    const uint32_t boff0 = (uint32_t)((warpn * 64 + g) * ROWB + tig * 4);

    const int NCH = DD / KCH;  // 8

    // ---------------- chunk issue ----------------
    // A raw: idx = tid + 256*it (it<8): row = idx>>4, c4 = idx&15
    // B:     idx = tid + 256*it (it<4): n = idx>>3, j = idx&7
    #define ISSUE_CHUNK(kc_, buf_) do {                                        \
        int k0_ = (kc_) * KCH;                                                 \
        _Pragma("unroll")                                                      \
        for (int it = 0; it < 8; it++) {                                       \
            int idx = tid + 256 * it;                                          \
            int row = idx >> 4, c4 = idx & 15;                                 \
            int gm = bm + row; if (gm > M - 1) gm = M - 1;                     \
            cp16(su + S_RAWA + row * 256 + c4 * 16,                            \
                 A + (size_t)gm * DD + k0_ + c4 * 4);                          \
        }                                                                      \
        _Pragma("unroll")                                                      \
        for (int it = 0; it < 4; it++) {                                       \
            int idx = tid + 256 * it;                                          \
            int n = idx >> 3, j = idx & 7;                                     \
            uint32_t d = n * ROWB + j * 16;                                    \
            const __nv_bfloat16* sh = Wth + (size_t)(bn + n) * DD + k0_ + j * 8; \
            const __nv_bfloat16* sl = Wtl + (size_t)(bn + n) * DD + k0_ + j * 8; \
            cp16(su + S_BH + (buf_) * 18432 + d, sh);                          \
            cp16(su + S_BL + (buf_) * 18432 + d, sl);                          \
        }                                                                      \
        cp_commit();                                                           \
    } while (0)

    // ---------------- convert raw A -> bf16 hi/lo (LN fused) ---------------
    #define CONVERT_CHUNK(kc_, buf_) do {                                      \
        int k0_ = (kc_) * KCH;                                                 \
        int row = tid >> 1;                                                    \
        int ko = (tid & 1) * 32;                                               \
        int gm = bm + row; if (gm > M - 1) gm = M - 1;                         \
        float2 s_ = st[gm];                                                    \
        _Pragma("unroll")                                                      \
        for (int j = 0; j < 8; j++) {                                          \
            int kk = ko + j * 4;                                               \
            float4 x = *(const float4*)(sRaw + row * KCH + kk);                \
            float4 g4 = *(const float4*)(sG + k0_ + kk);                       \
            float4 b4 = *(const float4*)(sB2 + k0_ + kk);                      \
            float v0 = (x.x - s_.x) * s_.y * g4.x + b4.x;                      \
            float v1 = (x.y - s_.x) * s_.y * g4.y + b4.y;                      \
            float v2 = (x.z - s_.x) * s_.y * g4.z + b4.z;                      \
            float v3 = (x.w - s_.x) * s_.y * g4.w + b4.w;                      \
            __nv_bfloat16 h0 = __float2bfloat16(v0), h1 = __float2bfloat16(v1);\
            __nv_bfloat16 h2 = __float2bfloat16(v2), h3 = __float2bfloat16(v3);\
            uint32_t hp0 = (uint32_t)__bfloat16_as_ushort(h0) |                \
                           ((uint32_t)__bfloat16_as_ushort(h1) << 16);         \
            uint32_t hp1 = (uint32_t)__bfloat16_as_ushort(h2) |                \
                           ((uint32_t)__bfloat16_as_ushort(h3) << 16);         \
            __nv_bfloat16 l0 = __float2bfloat16(v0 - __bfloat162float(h0));    \
            __nv_bfloat16 l1 = __float2bfloat16(v1 - __bfloat162float(h1));    \
            __nv_bfloat16 l2 = __float2bfloat16(v2 - __bfloat162float(h2));    \
            __nv_bfloat16 l3 = __float2bfloat16(v3 - __bfloat162float(h3));    \
            uint32_t lp0 = (uint32_t)__bfloat16_as_ushort(l0) |                \
                           ((uint32_t)__bfloat16_as_ushort(l1) << 16);         \
            uint32_t lp1 = (uint32_t)__bfloat16_as_ushort(l2) |                \
                           ((uint32_t)__bfloat16_as_ushort(l3) << 16);         \
            uint32_t d = row * ROWB + kk * 2;                                  \
            sts64(su + S_AH + (buf_) * 18432 + d, hp0, hp1);                   \
            sts64(su + S_AL + (buf_) * 18432 + d, lp0, lp1);                   \
        }                                                                      \
    } while (0)

    // prologue
    ISSUE_CHUNK(0, 0);
    cp_wait0();
    __syncthreads();
    CONVERT_CHUNK(0, 0);
    __syncthreads();

    for (int kc = 0; kc < NCH; kc++) {
        int buf = kc & 1;
        if (kc + 1 < NCH) ISSUE_CHUNK(kc + 1, buf ^ 1);

        // compute over buffer buf
        const uint32_t ah_base = su + S_AH + buf * 18432 + aoff0;
        const uint32_t al_base = su + S_AL + buf * 18432 + aoff0;
        const uint32_t bh_base = su + S_BH + buf * 18432 + boff0;
        const uint32_t bl_base = su + S_BL + buf * 18432 + boff0;
        #pragma unroll
        for (int ks = 0; ks < 4; ks++) {
            uint32_t kb = ks * 32;
            uint32_t ah[2][4], al[2][4];
            #pragma unroll
            for (int mi = 0; mi < 2; mi++) {
                uint32_t ba = ah_base + mi * (16 * ROWB) + kb;
                ah[mi][0] = lds32(ba);
                ah[mi][1] = lds32(ba + 8 * ROWB);
                ah[mi][2] = lds32(ba + 16);
                ah[mi][3] = lds32(ba + 8 * ROWB + 16);
                uint32_t bl = al_base + mi * (16 * ROWB) + kb;
                al[mi][0] = lds32(bl);
                al[mi][1] = lds32(bl + 8 * ROWB);
                al[mi][2] = lds32(bl + 16);
                al[mi][3] = lds32(bl + 8 * ROWB + 16);
            }
            #pragma unroll
            for (int ni = 0; ni < 8; ni++) {
                uint32_t bb = bh_base + ni * (8 * ROWB) + kb;
                uint32_t bh0 = lds32(bb), bh1 = lds32(bb + 16);
                uint32_t bc = bl_base + ni * (8 * ROWB) + kb;
                uint32_t bl0 = lds32(bc), bl1 = lds32(bc + 16);
                #pragma unroll
                for (int mi = 0; mi < 2; mi++) {
                    mma16816(acc[mi][ni], ah[mi], bh0, bh1);
                    mma16816(acc[mi][ni], ah[mi], bl0, bl1);
                    mma16816(acc[mi][ni], al[mi], bh0, bh1);
                }
            }
        }

        if (kc + 1 < NCH) {
            cp_wait0();
            __syncthreads();
            CONVERT_CHUNK(kc + 1, buf ^ 1);
            __syncthreads();
        }
    }

    // ---------------- epilogue: bias + relu -> gmem ------------------------
    #pragma unroll
    for (int mi = 0; mi < 2; mi++) {
        int row0 = bm + warpm * 32 + mi * 16 + g;
        #pragma unroll
        for (int ni = 0; ni < 8; ni++) {
            int col = bn + warpn * 64 + ni * 8 + 2 * tig;
            float bw0 = bw[col], bw1 = bw[col + 1];
            float o0 = acc[mi][ni][0] + bw0;
            float o1 = acc[mi][ni][1] + bw1;
            float o2 = acc[mi][ni][2] + bw0;
            float o3 = acc[mi][ni][3] + bw1;
            if (do_relu) {
                o0 = fmaxf(o0, 0.f); o1 = fmaxf(o1, 0.f);
                o2 = fmaxf(o2, 0.f); o3 = fmaxf(o3, 0.f);
            }
            if (row0 < M)
                *(float2*)(C + (size_t)row0 * DD + col) = make_float2(o0, o1);
            if (row0 + 8 < M)
                *(float2*)(C + (size_t)(row0 + 8) * DD + col) = make_float2(o2, o3);
        }
    }
}

// ---------------- pass 1: per-tile partial sums of relu(kp)*vp -------------
__global__ void kv_tilesum_kernel() {
    int t = blockIdx.x, b = blockIdx.y;
    int d = threadIdx.x;   // 512
    size_t base = ((size_t)b * LK) * DD + d;
    int l0 = t * TSZ;
    int lend = min(l0 + TSZ, LK);
    float s = 0.f;
    for (int l = l0; l < lend; l++) {
        size_t idx = base + (size_t)l * DD;
        s += g_rk[idx] * g_vp[idx];
    }
    g_tile[(b * NT + t) * DD + d] = s;
}

// ---------------- exclusive scan of tile sums ------------------------------
__global__ void tile_scan_kernel() {
    int d = threadIdx.x;   // 512
    int b = blockIdx.x;
    float run = 0.f;
    for (int t = 0; t < NT; t++) {
        int idx = (b * NT + t) * DD + d;
        float v = g_tile[idx];
        g_tile[idx] = run;
        run += v;
    }
}

// ---------------- pass 2: full exclusive prefix sums cs --------------------
__global__ void cs_kernel() {
    int t = blockIdx.x, b = blockIdx.y;
    int d = threadIdx.x;   // 512
    float run = g_tile[(b * NT + t) * DD + d];
    size_t kvb = ((size_t)b * LK) * DD + d;
    size_t csb = ((size_t)b * (LK + 1)) * DD + d;
    int l0 = t * TSZ;
    int lend = min(l0 + TSZ, LK);
    for (int l = l0; l < lend; l++) {
        g_cs[csb + (size_t)l * DD] = run;
        run += g_rk[kvb + (size_t)l * DD] * g_vp[kvb + (size_t)l * DD];
    }
    if (t == NT - 1) g_cs[csb + (size_t)LK * DD] = run;
}

// ---------------- out = relu(qp) * (cs[start+W] - cs[start]) ---------------
__global__ void combine_kernel(float* __restrict__ out) {
    int e = blockIdx.x * blockDim.x + threadIdx.x;
    const int D4 = DD / 4;
    if (e >= BB * LQ * D4) return;
    int d4 = e % D4;
    int i  = (e / D4) % LQ;
    int b  = e / (D4 * LQ);
    const int sup = LK - LQ - CACHE_LEN + 1;
    int start = sup + i;
    const float4* cs = reinterpret_cast<const float4*>(g_cs);
    size_t cb = ((size_t)b * (LK + 1)) * D4 + d4;
    float4 c1 = cs[cb + (size_t)(start + CACHE_LEN) * D4];
    float4 c0 = cs[cb + (size_t)start * D4];
    float4 rq = reinterpret_cast<const float4*>(g_rq)[e];
    float4 o;
    o.x = rq.x * (c1.x - c0.x);
    o.y = rq.y * (c1.y - c0.y);
    o.z = rq.z * (c1.z - c0.z);
    o.w = rq.w * (c1.w - c0.w);
    reinterpret_cast<float4*>(out)[e] = o;
}

// ---------------------------------------------------------------------------
extern "C" void kernel_launch(void* const* d_in, const int* in_sizes, int n_in,
                              void* d_out, int out_size) {
    const float* q   = (const float*)d_in[0];
    const float* k   = (const float*)d_in[1];
    const float* v   = (const float*)d_in[2];
    const float* gq  = (const float*)d_in[3];
    const float* bq  = (const float*)d_in[4];
    const float* gk  = (const float*)d_in[5];
    const float* bk  = (const float*)d_in[6];
    const float* gv  = (const float*)d_in[7];
    const float* bv  = (const float*)d_in[8];
    const float* Wq  = (const float*)d_in[9];
    const float* bwq = (const float*)d_in[10];
    const float* Wk  = (const float*)d_in[11];
    const float* bwk = (const float*)d_in[12];
    const float* Wv  = (const float*)d_in[13];
    const float* bwv = (const float*)d_in[14];

    void *stq_, *stk_, *stv_, *rq_, *rk_, *vp_, *wt_;
    cudaGetSymbolAddress(&stq_, g_st_q);
    cudaGetSymbolAddress(&stk_, g_st_k);
    cudaGetSymbolAddress(&stv_, g_st_v);
    cudaGetSymbolAddress(&rq_, g_rq);
    cudaGetSymbolAddress(&rk_, g_rk);
    cudaGetSymbolAddress(&vp_, g_vp);
    cudaGetSymbolAddress(&wt_, g_wt);
    float2* stq = (float2*)stq_;
    float2* stk = (float2*)stk_;
    float2* stv = (float2*)stv_;
    float* rq = (float*)rq_;
    float* rk = (float*)rk_;
    float* vp = (float*)vp_;
    __nv_bfloat16* wt = (__nv_bfloat16*)wt_;

    cudaFuncSetAttribute(gemm_mma_kernel,
                         cudaFuncAttributeMaxDynamicSharedMemorySize, S_TOTAL);

    const int MTQ = BB * LQ;     // 16384
    const int MTK = BB * LK;     // 20476

    wprep_kernel<<<dim3(DD / 32, DD / 32, 3), dim3(32, 8)>>>(Wq, Wk, Wv);

    rowstats_kernel<<<MTQ, 128>>>(q, stq, MTQ);
    rowstats_kernel<<<MTK, 128>>>(k, stk, MTK);
    rowstats_kernel<<<MTK, 128>>>(v, stv, MTK);

    __nv_bfloat16* wqh = wt;
    __nv_bfloat16* wql = wt + (size_t)DD * DD;
    __nv_bfloat16* wkh = wt + 2 * (size_t)DD * DD;
    __nv_bfloat16* wkl = wt + 3 * (size_t)DD * DD;
    __nv_bfloat16* wvh = wt + 4 * (size_t)DD * DD;
    __nv_bfloat16* wvl = wt + 5 * (size_t)DD * DD;

    dim3 gqg(DD / NTC, (MTQ + MT - 1) / MT);
    dim3 gkg(DD / NTC, (MTK + MT - 1) / MT);
    gemm_mma_kernel<<<gqg, 256, S_TOTAL>>>(q, stq, gq, bq, wqh, wql, bwq, rq, MTQ, 1);
    gemm_mma_kernel<<<gkg, 256, S_TOTAL>>>(k, stk, gk, bk, wkh, wkl, bwk, rk, MTK, 1);
    gemm_mma_kernel<<<gkg, 256, S_TOTAL>>>(v, stv, gv, bv, wvh, wvl, bwv, vp, MTK, 0);

    kv_tilesum_kernel<<<dim3(NT, BB), 512>>>();
    tile_scan_kernel<<<BB, 512>>>();
    cs_kernel<<<dim3(NT, BB), 512>>>();

    combine_kernel<<<(BB * LQ * (DD / 4) + 255) / 256, 256>>>((float*)d_out);
}

// round 5
// speedup vs baseline: 2.7407x; 1.4842x over previous
#include <cuda_runtime.h>
#include <cuda_bf16.h>
#include <cstdint>

// Problem constants (fixed by the dataset)
#define BB 4
#define LQ 4096
#define LK 5119
#define DD 512
#define CACHE_LEN 1024
#define EPSV 1e-5f

#define TSZ 64
#define NT ((LK + TSZ - 1) / TSZ)   // 80 tiles

// GEMM tiling
#define MT 128           // M rows per CTA
#define NTC 256          // N cols per CTA
#define KCH 64           // K chunk (64 bf16 = 128 bytes per row)

// smem per chunk-buffer: A_hi 16K | A_lo 16K | B_hi 32K | B_lo 32K
#define SBUF   98304
#define OFF_AH 0
#define OFF_AL 16384
#define OFF_BH 32768
#define OFF_BL 65536
#define S_TOTAL (2 * SBUF)   // 196608

// ---------------- scratch (__device__ globals) -----------------------------
__device__ float  g_rq[(size_t)BB * LQ * DD];        // relu(qp)
__device__ float  g_rk[(size_t)BB * LK * DD];        // relu(kp)
__device__ float  g_vp[(size_t)BB * LK * DD];        // vp
__device__ float  g_cs[(size_t)BB * (LK + 1) * DD];  // exclusive prefix sums
__device__ float  g_tile[BB * NT * DD];              // tile partial sums
__device__ __align__(256) __nv_bfloat16 g_wt[3 * 2 * DD * DD]; // [w][hi/lo][n][k]
// pre-normalized, pre-split A (bf16 hi/lo, row-major [m][k])
__device__ __align__(256) __nv_bfloat16 g_aqh[(size_t)BB * LQ * DD];
__device__ __align__(256) __nv_bfloat16 g_aql[(size_t)BB * LQ * DD];
__device__ __align__(256) __nv_bfloat16 g_akh[(size_t)BB * LK * DD];
__device__ __align__(256) __nv_bfloat16 g_akl[(size_t)BB * LK * DD];
__device__ __align__(256) __nv_bfloat16 g_avh[(size_t)BB * LK * DD];
__device__ __align__(256) __nv_bfloat16 g_avl[(size_t)BB * LK * DD];

// ================= helpers ================================================
__device__ __forceinline__ uint32_t smem_u32(const void* p) {
    uint32_t a;
    asm("{ .reg .u64 t; cvta.to.shared.u64 t, %1; cvt.u32.u64 %0, t; }" : "=r"(a) : "l"(p));
    return a;
}
__device__ __forceinline__ void cp16(uint32_t dst, const void* src) {
    asm volatile("cp.async.cg.shared.global [%0], [%1], 16;" :: "r"(dst), "l"(src));
}
__device__ __forceinline__ void cp_commit() {
    asm volatile("cp.async.commit_group;");
}
template <int N>
__device__ __forceinline__ void cp_wait() {
    asm volatile("cp.async.wait_group %0;" :: "n"(N));
}
__device__ __forceinline__ void ldsm4(uint32_t* r, uint32_t addr) {
    asm volatile("ldmatrix.sync.aligned.m8n8.x4.shared.b16 {%0,%1,%2,%3}, [%4];"
        : "=r"(r[0]), "=r"(r[1]), "=r"(r[2]), "=r"(r[3]) : "r"(addr));
}
__device__ __forceinline__ void mma16816(float* c, const uint32_t* a,
                                         uint32_t b0, uint32_t b1) {
    asm volatile(
        "mma.sync.aligned.m16n8k16.row.col.f32.bf16.bf16.f32 "
        "{%0,%1,%2,%3}, {%4,%5,%6,%7}, {%8,%9}, {%0,%1,%2,%3};"
        : "+f"(c[0]), "+f"(c[1]), "+f"(c[2]), "+f"(c[3])
        : "r"(a[0]), "r"(a[1]), "r"(a[2]), "r"(a[3]), "r"(b0), "r"(b1));
}

// ---------------- W prep: transpose + bf16 hi/lo split ---------------------
__global__ __launch_bounds__(256)
void wprep_kernel(const float* __restrict__ W0,
                  const float* __restrict__ W1,
                  const float* __restrict__ W2) {
    const float* W = (blockIdx.z == 0) ? W0 : (blockIdx.z == 1) ? W1 : W2;
    __shared__ float t[32][33];
    int n0 = blockIdx.x * 32, k0 = blockIdx.y * 32;
    int tx = threadIdx.x, ty = threadIdx.y;
    #pragma unroll
    for (int i = 0; i < 4; i++)
        t[ty + 8 * i][tx] = W[(size_t)(k0 + ty + 8 * i) * DD + n0 + tx];
    __syncthreads();
    __nv_bfloat16* hi = g_wt + (size_t)blockIdx.z * 2 * DD * DD;
    __nv_bfloat16* lo = hi + (size_t)DD * DD;
    #pragma unroll
    for (int i = 0; i < 4; i++) {
        int n = n0 + ty + 8 * i, k = k0 + tx;
        float v = t[tx][ty + 8 * i];
        __nv_bfloat16 h = __float2bfloat16(v);
        hi[(size_t)n * DD + k] = h;
        lo[(size_t)n * DD + k] = __float2bfloat16(v - __bfloat162float(h));
    }
}

// ---------------- fused LN + bf16 hi/lo split of A -------------------------
__global__ __launch_bounds__(128)
void lnprep_kernel(const float* __restrict__ x,
                   const float* __restrict__ gam, const float* __restrict__ bet,
                   __nv_bfloat16* __restrict__ hi, __nv_bfloat16* __restrict__ lo,
                   int nrows) {
    int row = blockIdx.x;
    if (row >= nrows) return;
    int tid = threadIdx.x;                  // 128, 4 floats each
    float4 v = reinterpret_cast<const float4*>(x + (size_t)row * DD)[tid];
    float s  = v.x + v.y + v.z + v.w;
    float s2 = v.x * v.x + v.y * v.y + v.z * v.z + v.w * v.w;
    #pragma unroll
    for (int o = 16; o > 0; o >>= 1) {
        s  += __shfl_down_sync(0xffffffffu, s, o);
        s2 += __shfl_down_sync(0xffffffffu, s2, o);
    }
    __shared__ float ss[4], ss2[4], mv[2];
    int w = tid >> 5, lane = tid & 31;
    if (lane == 0) { ss[w] = s; ss2[w] = s2; }
    __syncthreads();
    if (tid == 0) {
        float S = ss[0] + ss[1] + ss[2] + ss[3];
        float S2 = ss2[0] + ss2[1] + ss2[2] + ss2[3];
        float m = S / (float)DD;
        float var = S2 / (float)DD - m * m;
        mv[0] = m;
        mv[1] = rsqrtf(var + EPSV);
    }
    __syncthreads();
    float m = mv[0], r = mv[1];
    float4 g4 = reinterpret_cast<const float4*>(gam)[tid];
    float4 b4 = reinterpret_cast<const float4*>(bet)[tid];
    float y0 = (v.x - m) * r * g4.x + b4.x;
    float y1 = (v.y - m) * r * g4.y + b4.y;
    float y2 = (v.z - m) * r * g4.z + b4.z;
    float y3 = (v.w - m) * r * g4.w + b4.w;
    __nv_bfloat16 h0 = __float2bfloat16(y0), h1 = __float2bfloat16(y1);
    __nv_bfloat16 h2 = __float2bfloat16(y2), h3 = __float2bfloat16(y3);
    uint2 hp, lp;
    hp.x = (uint32_t)__bfloat16_as_ushort(h0) | ((uint32_t)__bfloat16_as_ushort(h1) << 16);
    hp.y = (uint32_t)__bfloat16_as_ushort(h2) | ((uint32_t)__bfloat16_as_ushort(h3) << 16);
    __nv_bfloat16 l0 = __float2bfloat16(y0 - __bfloat162float(h0));
    __nv_bfloat16 l1 = __float2bfloat16(y1 - __bfloat162float(h1));
    __nv_bfloat16 l2 = __float2bfloat16(y2 - __bfloat162float(h2));
    __nv_bfloat16 l3 = __float2bfloat16(y3 - __bfloat162float(h3));
    lp.x = (uint32_t)__bfloat16_as_ushort(l0) | ((uint32_t)__bfloat16_as_ushort(l1) << 16);
    lp.y = (uint32_t)__bfloat16_as_ushort(l2) | ((uint32_t)__bfloat16_as_ushort(l3) << 16);
    reinterpret_cast<uint2*>(hi + (size_t)row * DD)[tid] = hp;
    reinterpret_cast<uint2*>(lo + (size_t)row * DD)[tid] = lp;
}

// ---------------- HMMA split-bf16 GEMM, ldmatrix + cp.async ----------------
// C[m][n] = [relu]( A[m,:] @ Wt[n,:]^T + bw[n] ), A/W pre-split bf16 hi/lo
__global__ __launch_bounds__(512, 1)
void gemm_mma_kernel(const __nv_bfloat16* __restrict__ Ah,
                     const __nv_bfloat16* __restrict__ Al,
                     const __nv_bfloat16* __restrict__ Wth,
                     const __nv_bfloat16* __restrict__ Wtl,
                     const float* __restrict__ bw, float* __restrict__ C,
                     int M, int do_relu) {
    extern __shared__ char smem[];
    const uint32_t su = smem_u32(smem);

    const int tid = threadIdx.x;
    const int wid = tid >> 5, lane = tid & 31;
    const int warpm = wid & 3, warpn = wid >> 2;   // 4 x 4 warps, warp tile 32x64
    const int g = lane >> 2, tig = lane & 3;
    const int bm = blockIdx.y * MT, bn = blockIdx.x * NTC;

    float acc[2][8][4];
    #pragma unroll
    for (int mi = 0; mi < 2; mi++)
        #pragma unroll
        for (int ni = 0; ni < 8; ni++)
            #pragma unroll
            for (int r = 0; r < 4; r++) acc[mi][ni][r] = 0.f;

    // ldmatrix per-lane source rows
    const int arow = warpm * 32 + (lane & 7) + ((lane & 8) ? 8 : 0);
    const int acx  = (lane >> 4) & 1;              // k-col16 select
    const int arow7 = arow & 7;
    const int nrow = warpn * 64 + (lane & 7) + ((lane & 16) ? 8 : 0);
    const int ncx  = (lane >> 3) & 1;
    const int nrow7 = nrow & 7;

    const int NCH = DD / KCH;   // 8

    #define ISSUE_CHUNK(kc_, buf_) do {                                        \
        int k0_ = (kc_) * KCH;                                                 \
        uint32_t db_ = su + (buf_) * SBUF;                                     \
        _Pragma("unroll")                                                      \
        for (int it = 0; it < 2; it++) {                                       \
            int idx = tid + 512 * it;                                          \
            int row = idx >> 3, c = idx & 7;                                   \
            int gm = bm + row; if (gm > M - 1) gm = M - 1;                     \
            uint32_t sw = (uint32_t)(row * 128 + ((c ^ (row & 7)) << 4));      \
            const __nv_bfloat16* sh = Ah + (size_t)gm * DD + k0_ + c * 8;      \
            const __nv_bfloat16* sl = Al + (size_t)gm * DD + k0_ + c * 8;      \
            cp16(db_ + OFF_AH + sw, sh);                                       \
            cp16(db_ + OFF_AL + sw, sl);                                       \
        }                                                                      \
        _Pragma("unroll")                                                      \
        for (int it = 0; it < 4; it++) {                                       \
            int idx = tid + 512 * it;                                          \
            int n = idx >> 3, c = idx & 7;                                     \
            uint32_t sw = (uint32_t)(n * 128 + ((c ^ (n & 7)) << 4));          \
            const __nv_bfloat16* sh = Wth + (size_t)(bn + n) * DD + k0_ + c * 8; \
            const __nv_bfloat16* sl = Wtl + (size_t)(bn + n) * DD + k0_ + c * 8; \
            cp16(db_ + OFF_BH + sw, sh);                                       \
            cp16(db_ + OFF_BL + sw, sl);                                       \
        }                                                                      \
        cp_commit();                                                           \
    } while (0)

    ISSUE_CHUNK(0, 0);

    for (int kc = 0; kc < NCH; kc++) {
        int buf = kc & 1;
        if (kc + 1 < NCH) { ISSUE_CHUNK(kc + 1, buf ^ 1); cp_wait<1>(); }
        else cp_wait<0>();
        __syncthreads();

        const uint32_t db = su + buf * SBUF;
        const uint32_t a_rowb = db + (uint32_t)(arow * 128);
        const uint32_t b_rowb = db + (uint32_t)(nrow * 128);

        #pragma unroll
        for (int ks = 0; ks < 4; ks++) {
            uint32_t ah[2][4], al[2][4];
            uint32_t a_sw = (uint32_t)(((ks * 2 + acx) ^ arow7) << 4);
            #pragma unroll
            for (int mi = 0; mi < 2; mi++) {
                uint32_t base = a_rowb + (uint32_t)(mi * 16 * 128) + a_sw;
                ldsm4(ah[mi], base + OFF_AH);
                ldsm4(al[mi], base + OFF_AL);
            }
            uint32_t b_sw = (uint32_t)(((ks * 2 + ncx) ^ nrow7) << 4);
            #pragma unroll
            for (int p = 0; p < 4; p++) {
                uint32_t bb = b_rowb + (uint32_t)(p * 16 * 128) + b_sw;
                uint32_t bh[4], bl[4];
                ldsm4(bh, bb + OFF_BH);
                ldsm4(bl, bb + OFF_BL);
                #pragma unroll
                for (int mi = 0; mi < 2; mi++) {
                    mma16816(acc[mi][2 * p],     ah[mi], bh[0], bh[1]);
                    mma16816(acc[mi][2 * p],     ah[mi], bl[0], bl[1]);
                    mma16816(acc[mi][2 * p],     al[mi], bh[0], bh[1]);
                    mma16816(acc[mi][2 * p + 1], ah[mi], bh[2], bh[3]);
                    mma16816(acc[mi][2 * p + 1], ah[mi], bl[2], bl[3]);
                    mma16816(acc[mi][2 * p + 1], al[mi], bh[2], bh[3]);
                }
            }
        }
        __syncthreads();
    }

    // ---------------- epilogue: bias + relu -> gmem ------------------------
    #pragma unroll
    for (int mi = 0; mi < 2; mi++) {
        int row0 = bm + warpm * 32 + mi * 16 + g;
        #pragma unroll
        for (int ni = 0; ni < 8; ni++) {
            int col = bn + warpn * 64 + ni * 8 + 2 * tig;
            float bw0 = bw[col], bw1 = bw[col + 1];
            float o0 = acc[mi][ni][0] + bw0;
            float o1 = acc[mi][ni][1] + bw1;
            float o2 = acc[mi][ni][2] + bw0;
            float o3 = acc[mi][ni][3] + bw1;
            if (do_relu) {
                o0 = fmaxf(o0, 0.f); o1 = fmaxf(o1, 0.f);
                o2 = fmaxf(o2, 0.f); o3 = fmaxf(o3, 0.f);
            }
            if (row0 < M)
                *(float2*)(C + (size_t)row0 * DD + col) = make_float2(o0, o1);
            if (row0 + 8 < M)
                *(float2*)(C + (size_t)(row0 + 8) * DD + col) = make_float2(o2, o3);
        }
    }
}

// ---------------- pass 1: per-tile partial sums of relu(kp)*vp -------------
__global__ __launch_bounds__(512)
void kv_tilesum_kernel() {
    int t = blockIdx.x, b = blockIdx.y;
    int d = threadIdx.x;   // 512
    size_t base = ((size_t)b * LK) * DD + d;
    int l0 = t * TSZ;
    int lend = min(l0 + TSZ, LK);
    float s = 0.f;
    for (int l = l0; l < lend; l++) {
        size_t idx = base + (size_t)l * DD;
        s += g_rk[idx] * g_vp[idx];
    }
    g_tile[(b * NT + t) * DD + d] = s;
}

// ---------------- exclusive scan of tile sums (streaming) ------------------
__global__ __launch_bounds__(512)
void tile_scan_kernel() {
    int d = threadIdx.x;   // 512
    int b = blockIdx.x;
    float run = 0.f;
    for (int t = 0; t < NT; t++) {
        int idx = (b * NT + t) * DD + d;
        float v = g_tile[idx];
        g_tile[idx] = run;
        run += v;
    }
}

// ---------------- pass 2: full exclusive prefix sums cs --------------------
__global__ __launch_bounds__(512)
void cs_kernel() {
    int t = blockIdx.x, b = blockIdx.y;
    int d = threadIdx.x;   // 512
    float run = g_tile[(b * NT + t) * DD + d];
    size_t kvb = ((size_t)b * LK) * DD + d;
    size_t csb = ((size_t)b * (LK + 1)) * DD + d;
    int l0 = t * TSZ;
    int lend = min(l0 + TSZ, LK);
    for (int l = l0; l < lend; l++) {
        g_cs[csb + (size_t)l * DD] = run;
        run += g_rk[kvb + (size_t)l * DD] * g_vp[kvb + (size_t)l * DD];
    }
    if (t == NT - 1) g_cs[csb + (size_t)LK * DD] = run;
}

// ---------------- out = relu(qp) * (cs[start+W] - cs[start]) ---------------
__global__ __launch_bounds__(256)
void combine_kernel(float* __restrict__ out) {
    int e = blockIdx.x * blockDim.x + threadIdx.x;
    const int D4 = DD / 4;
    if (e >= BB * LQ * D4) return;
    int d4 = e % D4;
    int i  = (e / D4) % LQ;
    int b  = e / (D4 * LQ);
    const int sup = LK - LQ - CACHE_LEN + 1;
    int start = sup + i;
    const float4* cs = reinterpret_cast<const float4*>(g_cs);
    size_t cb = ((size_t)b * (LK + 1)) * D4 + d4;
    float4 c1 = cs[cb + (size_t)(start + CACHE_LEN) * D4];
    float4 c0 = cs[cb + (size_t)start * D4];
    float4 rq = reinterpret_cast<const float4*>(g_rq)[e];
    float4 o;
    o.x = rq.x * (c1.x - c0.x);
    o.y = rq.y * (c1.y - c0.y);
    o.z = rq.z * (c1.z - c0.z);
    o.w = rq.w * (c1.w - c0.w);
    reinterpret_cast<float4*>(out)[e] = o;
}

// ---------------------------------------------------------------------------
extern "C" void kernel_launch(void* const* d_in, const int* in_sizes, int n_in,
                              void* d_out, int out_size) {
    const float* q   = (const float*)d_in[0];
    const float* k   = (const float*)d_in[1];
    const float* v   = (const float*)d_in[2];
    const float* gq  = (const float*)d_in[3];
    const float* bq  = (const float*)d_in[4];
    const float* gk  = (const float*)d_in[5];
    const float* bk  = (const float*)d_in[6];
    const float* gv  = (const float*)d_in[7];
    const float* bv  = (const float*)d_in[8];
    const float* Wq  = (const float*)d_in[9];
    const float* bwq = (const float*)d_in[10];
    const float* Wk  = (const float*)d_in[11];
    const float* bwk = (const float*)d_in[12];
    const float* Wv  = (const float*)d_in[13];
    const float* bwv = (const float*)d_in[14];

    void *rq_, *rk_, *vp_, *wt_;
    void *aqh_, *aql_, *akh_, *akl_, *avh_, *avl_;
    cudaGetSymbolAddress(&rq_, g_rq);
    cudaGetSymbolAddress(&rk_, g_rk);
    cudaGetSymbolAddress(&vp_, g_vp);
    cudaGetSymbolAddress(&wt_, g_wt);
    cudaGetSymbolAddress(&aqh_, g_aqh);
    cudaGetSymbolAddress(&aql_, g_aql);
    cudaGetSymbolAddress(&akh_, g_akh);
    cudaGetSymbolAddress(&akl_, g_akl);
    cudaGetSymbolAddress(&avh_, g_avh);
    cudaGetSymbolAddress(&avl_, g_avl);
    float* rq = (float*)rq_;
    float* rk = (float*)rk_;
    float* vp = (float*)vp_;
    __nv_bfloat16* wt = (__nv_bfloat16*)wt_;

    cudaFuncSetAttribute(gemm_mma_kernel,
                         cudaFuncAttributeMaxDynamicSharedMemorySize, S_TOTAL);

    const int MTQ = BB * LQ;     // 16384
    const int MTK = BB * LK;     // 20476

    wprep_kernel<<<dim3(DD / 32, DD / 32, 3), dim3(32, 8)>>>(Wq, Wk, Wv);

    lnprep_kernel<<<MTQ, 128>>>(q, gq, bq, (__nv_bfloat16*)aqh_, (__nv_bfloat16*)aql_, MTQ);
    lnprep_kernel<<<MTK, 128>>>(k, gk, bk, (__nv_bfloat16*)akh_, (__nv_bfloat16*)akl_, MTK);
    lnprep_kernel<<<MTK, 128>>>(v, gv, bv, (__nv_bfloat16*)avh_, (__nv_bfloat16*)avl_, MTK);

    __nv_bfloat16* wqh = wt;
    __nv_bfloat16* wql = wt + (size_t)DD * DD;
    __nv_bfloat16* wkh = wt + 2 * (size_t)DD * DD;
    __nv_bfloat16* wkl = wt + 3 * (size_t)DD * DD;
    __nv_bfloat16* wvh = wt + 4 * (size_t)DD * DD;
    __nv_bfloat16* wvl = wt + 5 * (size_t)DD * DD;

    dim3 gqg(DD / NTC, (MTQ + MT - 1) / MT);
    dim3 gkg(DD / NTC, (MTK + MT - 1) / MT);
    gemm_mma_kernel<<<gqg, 512, S_TOTAL>>>((__nv_bfloat16*)aqh_, (__nv_bfloat16*)aql_,
                                           wqh, wql, bwq, rq, MTQ, 1);
    gemm_mma_kernel<<<gkg, 512, S_TOTAL>>>((__nv_bfloat16*)akh_, (__nv_bfloat16*)akl_,
                                           wkh, wkl, bwk, rk, MTK, 1);
    gemm_mma_kernel<<<gkg, 512, S_TOTAL>>>((__nv_bfloat16*)avh_, (__nv_bfloat16*)avl_,
                                           wvh, wvl, bwv, vp, MTK, 0);

    kv_tilesum_kernel<<<dim3(NT, BB), 512>>>();
    tile_scan_kernel<<<BB, 512>>>();
    cs_kernel<<<dim3(NT, BB), 512>>>();

    combine_kernel<<<(BB * LQ * (DD / 4) + 255) / 256, 256>>>((float*)d_out);
}

// round 7
// speedup vs baseline: 2.8569x; 1.0424x over previous
#include <cuda_runtime.h>
#include <cuda_bf16.h>
#include <cstdint>

// Problem constants (fixed by the dataset)
#define BB 4
#define LQ 4096
#define LK 5119
#define DD 512
#define CACHE_LEN 1024
#define EPSV 1e-5f

#define TSZ 64
#define NT ((LK + TSZ - 1) / TSZ)   // 80 tiles
#define NQT (LQ / TSZ)              // 64 output tiles

// GEMM tiling
#define MT 128           // M rows per CTA
#define NTC 256          // N cols per CTA
#define KCH 32           // K chunk (32 bf16 = 64 bytes per row)
#define NCH (DD / KCH)   // 16 chunks
#define NSTAGE 4

// smem per chunk-buffer: A_hi 8K | A_lo 8K | B_hi 16K | B_lo 16K
#define SBUF   49152
#define OFF_AH 0
#define OFF_AL 8192
#define OFF_BH 16384
#define OFF_BL 32768
#define S_TOTAL (NSTAGE * SBUF)   // 196608

// ---------------- scratch (__device__ globals) -----------------------------
__device__ float  g_rq[(size_t)BB * LQ * DD];        // relu(qp)
__device__ float  g_rk[(size_t)BB * LK * DD];        // relu(kp)
__device__ float  g_kv[(size_t)BB * LK * DD];        // relu(kp)*vp
__device__ float  g_tile[BB * NT * DD];              // tile prefix sums
__device__ __align__(256) __nv_bfloat16 g_wt[3 * 2 * DD * DD]; // [w][hi/lo][n][k]
// pre-normalized, pre-split A (bf16 hi/lo, row-major [m][k])
__device__ __align__(256) __nv_bfloat16 g_aqh[(size_t)BB * LQ * DD];
__device__ __align__(256) __nv_bfloat16 g_aql[(size_t)BB * LQ * DD];
__device__ __align__(256) __nv_bfloat16 g_akh[(size_t)BB * LK * DD];
__device__ __align__(256) __nv_bfloat16 g_akl[(size_t)BB * LK * DD];
__device__ __align__(256) __nv_bfloat16 g_avh[(size_t)BB * LK * DD];
__device__ __align__(256) __nv_bfloat16 g_avl[(size_t)BB * LK * DD];

// ================= helpers ================================================
__device__ __forceinline__ uint32_t smem_u32(const void* p) {
    uint32_t a;
    asm("{ .reg .u64 t; cvta.to.shared.u64 t, %1; cvt.u32.u64 %0, t; }" : "=r"(a) : "l"(p));
    return a;
}
__device__ __forceinline__ void cp16(uint32_t dst, const void* src) {
    asm volatile("cp.async.cg.shared.global [%0], [%1], 16;" :: "r"(dst), "l"(src));
}
__device__ __forceinline__ void cp_commit() {
    asm volatile("cp.async.commit_group;");
}
template <int N>
__device__ __forceinline__ void cp_wait() {
    asm volatile("cp.async.wait_group %0;" :: "n"(N));
}
__device__ __forceinline__ void ldsm4(uint32_t* r, uint32_t addr) {
    asm volatile("ldmatrix.sync.aligned.m8n8.x4.shared.b16 {%0,%1,%2,%3}, [%4];"
        : "=r"(r[0]), "=r"(r[1]), "=r"(r[2]), "=r"(r[3]) : "r"(addr));
}
__device__ __forceinline__ void mma16816(float* c, const uint32_t* a,
                                         uint32_t b0, uint32_t b1) {
    asm volatile(
        "mma.sync.aligned.m16n8k16.row.col.f32.bf16.bf16.f32 "
        "{%0,%1,%2,%3}, {%4,%5,%6,%7}, {%8,%9}, {%0,%1,%2,%3};"
        : "+f"(c[0]), "+f"(c[1]), "+f"(c[2]), "+f"(c[3])
        : "r"(a[0]), "r"(a[1]), "r"(a[2]), "r"(a[3]), "r"(b0), "r"(b1));
}

// ---------------- W prep: transpose + bf16 hi/lo split ---------------------
__global__ __launch_bounds__(256)
void wprep_kernel(const float* __restrict__ W0,
                  const float* __restrict__ W1,
                  const float* __restrict__ W2) {
    const float* W = (blockIdx.z == 0) ? W0 : (blockIdx.z == 1) ? W1 : W2;
    __shared__ float t[32][33];
    int n0 = blockIdx.x * 32, k0 = blockIdx.y * 32;
    int tx = threadIdx.x, ty = threadIdx.y;
    #pragma unroll
    for (int i = 0; i < 4; i++)
        t[ty + 8 * i][tx] = W[(size_t)(k0 + ty + 8 * i) * DD + n0 + tx];
    __syncthreads();
    __nv_bfloat16* hi = g_wt + (size_t)blockIdx.z * 2 * DD * DD;
    __nv_bfloat16* lo = hi + (size_t)DD * DD;
    #pragma unroll
    for (int i = 0; i < 4; i++) {
        int n = n0 + ty + 8 * i, k = k0 + tx;
        float v = t[tx][ty + 8 * i];
        __nv_bfloat16 h = __float2bfloat16(v);
        hi[(size_t)n * DD + k] = h;
        lo[(size_t)n * DD + k] = __float2bfloat16(v - __bfloat162float(h));
    }
}

// ---------------- fused LN + bf16 hi/lo split (warp per row) ---------------
__global__ __launch_bounds__(256)
void lnprep_kernel(const float* __restrict__ x,
                   const float* __restrict__ gam, const float* __restrict__ bet,
                   __nv_bfloat16* __restrict__ hi, __nv_bfloat16* __restrict__ lo,
                   int nrows) {
    int wid = threadIdx.x >> 5, lane = threadIdx.x & 31;
    int row = blockIdx.x * 8 + wid;
    if (row >= nrows) return;
    const float4* xr = reinterpret_cast<const float4*>(x + (size_t)row * DD);
    float4 v[4];
    float s = 0.f, s2 = 0.f;
    #pragma unroll
    for (int j = 0; j < 4; j++) {
        v[j] = xr[j * 32 + lane];
        s  += v[j].x + v[j].y + v[j].z + v[j].w;
        s2 += v[j].x * v[j].x + v[j].y * v[j].y + v[j].z * v[j].z + v[j].w * v[j].w;
    }
    #pragma unroll
    for (int o = 16; o > 0; o >>= 1) {
        s  += __shfl_xor_sync(0xffffffffu, s, o);
        s2 += __shfl_xor_sync(0xffffffffu, s2, o);
    }
    float m = s / (float)DD;
    float r = rsqrtf(s2 / (float)DD - m * m + EPSV);
    const float4* gr = reinterpret_cast<const float4*>(gam);
    const float4* br = reinterpret_cast<const float4*>(bet);
    uint2* hp = reinterpret_cast<uint2*>(hi + (size_t)row * DD);
    uint2* lp = reinterpret_cast<uint2*>(lo + (size_t)row * DD);
    #pragma unroll
    for (int j = 0; j < 4; j++) {
        float4 g4 = gr[j * 32 + lane];
        float4 b4 = br[j * 32 + lane];
        float y0 = (v[j].x - m) * r * g4.x + b4.x;
        float y1 = (v[j].y - m) * r * g4.y + b4.y;
        float y2 = (v[j].z - m) * r * g4.z + b4.z;
        float y3 = (v[j].w - m) * r * g4.w + b4.w;
        __nv_bfloat16 h0 = __float2bfloat16(y0), h1 = __float2bfloat16(y1);
        __nv_bfloat16 h2 = __float2bfloat16(y2), h3 = __float2bfloat16(y3);
        uint2 hv, lv;
        hv.x = (uint32_t)__bfloat16_as_ushort(h0) | ((uint32_t)__bfloat16_as_ushort(h1) << 16);
        hv.y = (uint32_t)__bfloat16_as_ushort(h2) | ((uint32_t)__bfloat16_as_ushort(h3) << 16);
        __nv_bfloat16 l0 = __float2bfloat16(y0 - __bfloat162float(h0));
        __nv_bfloat16 l1 = __float2bfloat16(y1 - __bfloat162float(h1));
        __nv_bfloat16 l2 = __float2bfloat16(y2 - __bfloat162float(h2));
        __nv_bfloat16 l3 = __float2bfloat16(y3 - __bfloat162float(h3));
        lv.x = (uint32_t)__bfloat16_as_ushort(l0) | ((uint32_t)__bfloat16_as_ushort(l1) << 16);
        lv.y = (uint32_t)__bfloat16_as_ushort(l2) | ((uint32_t)__bfloat16_as_ushort(l3) << 16);
        hp[j * 32 + lane] = hv;
        lp[j * 32 + lane] = lv;
    }
}

// ---------------- HMMA split-bf16 GEMM, 4-stage cp.async pipeline ----------
// C[m][n] = [relu]( A[m,:] @ Wt[n,:]^T + bw[n] ) [* mult[m,n]]
__global__ __launch_bounds__(512, 1)
void gemm_mma_kernel(const __nv_bfloat16* __restrict__ Ah,
                     const __nv_bfloat16* __restrict__ Al,
                     const __nv_bfloat16* __restrict__ Wth,
                     const __nv_bfloat16* __restrict__ Wtl,
                     const float* __restrict__ bw, float* __restrict__ C,
                     const float* __restrict__ mult,
                     int M, int do_relu) {
    extern __shared__ char smem[];
    const uint32_t su = smem_u32(smem);

    const int tid = threadIdx.x;
    const int wid = tid >> 5, lane = tid & 31;
    const int warpm = wid & 3, warpn = wid >> 2;   // 4 x 4 warps, warp tile 32x64
    const int g = lane >> 2, tig = lane & 3;
    const int bm = blockIdx.y * MT, bn = blockIdx.x * NTC;

    float acc[2][8][4];
    #pragma unroll
    for (int mi = 0; mi < 2; mi++)
        #pragma unroll
        for (int ni = 0; ni < 8; ni++)
            #pragma unroll
            for (int r = 0; r < 4; r++) acc[mi][ni][r] = 0.f;

    // ldmatrix per-lane source rows (64B rows, XOR swizzle on (row>>1)&3)
    const int arow = warpm * 32 + (lane & 7) + ((lane & 8) ? 8 : 0);
    const int acx  = (lane >> 4) & 1;              // k-col16 select
    const int axor = (arow >> 1) & 3;
    const int nrow = warpn * 64 + (lane & 7) + ((lane & 16) ? 8 : 0);
    const int ncx  = (lane >> 3) & 1;
    const int bxor = (nrow >> 1) & 3;

    #define ISSUE_CHUNK(kc_) do {                                              \
        int k0_ = (kc_) * KCH;                                                 \
        uint32_t db_ = su + ((kc_) & (NSTAGE - 1)) * SBUF;                     \
        {   /* A: 128 rows x 4 c16, one op per thread per split */             \
            int row = tid >> 2, c = tid & 3;                                   \
            int gm = bm + row; if (gm > M - 1) gm = M - 1;                     \
            uint32_t sw = (uint32_t)(row * 64 + ((c ^ ((row >> 1) & 3)) << 4));\
            cp16(db_ + OFF_AH + sw, Ah + (size_t)gm * DD + k0_ + c * 8);       \
            cp16(db_ + OFF_AL + sw, Al + (size_t)gm * DD + k0_ + c * 8);       \
        }                                                                      \
        _Pragma("unroll")                                                      \
        for (int it = 0; it < 2; it++) {   /* B: 256 rows x 4 c16 */           \
            int idx = tid + 512 * it;                                          \
            int n = idx >> 2, c = idx & 3;                                     \
            uint32_t sw = (uint32_t)(n * 64 + ((c ^ ((n >> 1) & 3)) << 4));    \
            cp16(db_ + OFF_BH + sw, Wth + (size_t)(bn + n) * DD + k0_ + c * 8);\
            cp16(db_ + OFF_BL + sw, Wtl + (size_t)(bn + n) * DD + k0_ + c * 8);\
        }                                                                      \
        cp_commit();                                                           \
    } while (0)

    ISSUE_CHUNK(0);
    ISSUE_CHUNK(1);
    ISSUE_CHUNK(2);

    for (int kc = 0; kc < NCH; kc++) {
        if (kc + 3 < NCH)      { ISSUE_CHUNK(kc + 3); cp_wait<3>(); }
        else if (kc + 2 < NCH) cp_wait<2>();
        else if (kc + 1 < NCH) cp_wait<1>();
        else                   cp_wait<0>();
        __syncthreads();

        const uint32_t db = su + (kc & (NSTAGE - 1)) * SBUF;
        const uint32_t a_rowb = db + (uint32_t)(arow * 64);
        const uint32_t b_rowb = db + (uint32_t)(nrow * 64);

        #pragma unroll
        for (int ks = 0; ks < 2; ks++) {
            uint32_t ah[2][4], al[2][4];
            uint32_t a_sw = (uint32_t)(((ks * 2 + acx) ^ axor) << 4);
            #pragma unroll
            for (int mi = 0; mi < 2; mi++) {
                uint32_t base = a_rowb + (uint32_t)(mi * 16 * 64) + a_sw;
                ldsm4(ah[mi], base + OFF_AH);
                ldsm4(al[mi], base + OFF_AL);
            }
            uint32_t b_sw = (uint32_t)(((ks * 2 + ncx) ^ bxor) << 4);
            #pragma unroll
            for (int p = 0; p < 4; p++) {
                uint32_t bb = b_rowb + (uint32_t)(p * 16 * 64) + b_sw;
                uint32_t bh[4], bl[4];
                ldsm4(bh, bb + OFF_BH);
                ldsm4(bl, bb + OFF_BL);
                #pragma unroll
                for (int mi = 0; mi < 2; mi++) {
                    mma16816(acc[mi][2 * p],     ah[mi], bh[0], bh[1]);
                    mma16816(acc[mi][2 * p],     ah[mi], bl[0], bl[1]);
                    mma16816(acc[mi][2 * p],     al[mi], bh[0], bh[1]);
                    mma16816(acc[mi][2 * p + 1], ah[mi], bh[2], bh[3]);
                    mma16816(acc[mi][2 * p + 1], ah[mi], bl[2], bl[3]);
                    mma16816(acc[mi][2 * p + 1], al[mi], bh[2], bh[3]);
                }
            }
        }
        __syncthreads();
    }

    // ---------------- epilogue: bias [+relu] [*mult] -> gmem ---------------
    #pragma unroll
    for (int mi = 0; mi < 2; mi++) {
        int row0 = bm + warpm * 32 + mi * 16 + g;
        #pragma unroll
        for (int ni = 0; ni < 8; ni++) {
            int col = bn + warpn * 64 + ni * 8 + 2 * tig;
            float bw0 = bw[col], bw1 = bw[col + 1];
            float o0 = acc[mi][ni][0] + bw0;
            float o1 = acc[mi][ni][1] + bw1;
            float o2 = acc[mi][ni][2] + bw0;
            float o3 = acc[mi][ni][3] + bw1;
            if (do_relu) {
                o0 = fmaxf(o0, 0.f); o1 = fmaxf(o1, 0.f);
                o2 = fmaxf(o2, 0.f); o3 = fmaxf(o3, 0.f);
            }
            if (mult) {
                if (row0 < M) {
                    float2 m0 = *(const float2*)(mult + (size_t)row0 * DD + col);
                    o0 *= m0.x; o1 *= m0.y;
                }
                if (row0 + 8 < M) {
                    float2 m1 = *(const float2*)(mult + (size_t)(row0 + 8) * DD + col);
                    o2 *= m1.x; o3 *= m1.y;
                }
            }
            if (row0 < M)
                *(float2*)(C + (size_t)row0 * DD + col) = make_float2(o0, o1);
            if (row0 + 8 < M)
                *(float2*)(C + (size_t)(row0 + 8) * DD + col) = make_float2(o2, o3);
        }
    }
}

// ---------------- per-tile partial sums of kv ------------------------------
__global__ __launch_bounds__(512)
void kv_tilesum_kernel() {
    int t = blockIdx.x, b = blockIdx.y;
    int d = threadIdx.x;   // 512
    size_t base = ((size_t)b * LK) * DD + d;
    int l0 = t * TSZ;
    int lend = min(l0 + TSZ, LK);
    float s = 0.f;
    for (int l = l0; l < lend; l++)
        s += g_kv[base + (size_t)l * DD];
    g_tile[(b * NT + t) * DD + d] = s;
}

// ---------------- exclusive scan of tile sums (streaming) ------------------
__global__ __launch_bounds__(512)
void tile_scan_kernel() {
    int d = threadIdx.x;   // 512
    int b = blockIdx.x;
    float run = 0.f;
    for (int t = 0; t < NT; t++) {
        int idx = (b * NT + t) * DD + d;
        float v = g_tile[idx];
        g_tile[idx] = run;
        run += v;
    }
}

// ---------------- fused windowed-sum + relu(qp) multiply -> out ------------
// out[b,i,d] = rq[b,i,d] * (cs[i+1024] - cs[i]);  sup = 0 for these shapes
__global__ __launch_bounds__(512)
void winout_kernel(float* __restrict__ out) {
    int t = blockIdx.x, b = blockIdx.y;   // t in 0..NQT-1
    int d = threadIdx.x;                  // 512
    float run_lo = g_tile[(b * NT + t) * DD + d];
    float run_hi = g_tile[(b * NT + t + CACHE_LEN / TSZ) * DD + d];
    size_t kvb = ((size_t)b * LK) * DD + d;
    size_t qb  = ((size_t)b * LQ) * DD + d;
    #pragma unroll 4
    for (int r = 0; r < TSZ; r++) {
        int i = t * TSZ + r;
        float w = run_hi - run_lo;
        out[qb + (size_t)i * DD] = g_rq[qb + (size_t)i * DD] * w;
        run_lo += g_kv[kvb + (size_t)i * DD];
        int ihi = i + CACHE_LEN;
        if (ihi < LK) run_hi += g_kv[kvb + (size_t)ihi * DD];
    }
}

// ---------------------------------------------------------------------------
extern "C" void kernel_launch(void* const* d_in, const int* in_sizes, int n_in,
                              void* d_out, int out_size) {
    const float* q   = (const float*)d_in[0];
    const float* k   = (const float*)d_in[1];
    const float* v   = (const float*)d_in[2];
    const float* gq  = (const float*)d_in[3];
    const float* bq  = (const float*)d_in[4];
    const float* gk  = (const float*)d_in[5];
    const float* bk  = (const float*)d_in[6];
    const float* gv  = (const float*)d_in[7];
    const float* bv  = (const float*)d_in[8];
    const float* Wq  = (const float*)d_in[9];
    const float* bwq = (const float*)d_in[10];
    const float* Wk  = (const float*)d_in[11];
    const float* bwk = (const float*)d_in[12];
    const float* Wv  = (const float*)d_in[13];
    const float* bwv = (const float*)d_in[14];

    void *rq_, *rk_, *kv_, *wt_;
    void *aqh_, *aql_, *akh_, *akl_, *avh_, *avl_;
    cudaGetSymbolAddress(&rq_, g_rq);
    cudaGetSymbolAddress(&rk_, g_rk);
    cudaGetSymbolAddress(&kv_, g_kv);
    cudaGetSymbolAddress(&wt_, g_wt);
    cudaGetSymbolAddress(&aqh_, g_aqh);
    cudaGetSymbolAddress(&aql_, g_aql);
    cudaGetSymbolAddress(&akh_, g_akh);
    cudaGetSymbolAddress(&akl_, g_akl);
    cudaGetSymbolAddress(&avh_, g_avh);
    cudaGetSymbolAddress(&avl_, g_avl);
    float* rq = (float*)rq_;
    float* rk = (float*)rk_;
    float* kv = (float*)kv_;
    __nv_bfloat16* wt = (__nv_bfloat16*)wt_;

    cudaFuncSetAttribute(gemm_mma_kernel,
                         cudaFuncAttributeMaxDynamicSharedMemorySize, S_TOTAL);

    const int MTQ = BB * LQ;     // 16384
    const int MTK = BB * LK;     // 20476

    wprep_kernel<<<dim3(DD / 32, DD / 32, 3), dim3(32, 8)>>>(Wq, Wk, Wv);

    lnprep_kernel<<<(MTQ + 7) / 8, 256>>>(q, gq, bq, (__nv_bfloat16*)aqh_, (__nv_bfloat16*)aql_, MTQ);
    lnprep_kernel<<<(MTK + 7) / 8, 256>>>(k, gk, bk, (__nv_bfloat16*)akh_, (__nv_bfloat16*)akl_, MTK);
    lnprep_kernel<<<(MTK + 7) / 8, 256>>>(v, gv, bv, (__nv_bfloat16*)avh_, (__nv_bfloat16*)avl_, MTK);

    __nv_bfloat16* wqh = wt;
    __nv_bfloat16* wql = wt + (size_t)DD * DD;
    __nv_bfloat16* wkh = wt + 2 * (size_t)DD * DD;
    __nv_bfloat16* wkl = wt + 3 * (size_t)DD * DD;
    __nv_bfloat16* wvh = wt + 4 * (size_t)DD * DD;
    __nv_bfloat16* wvl = wt + 5 * (size_t)DD * DD;

    dim3 gqg(DD / NTC, (MTQ + MT - 1) / MT);
    dim3 gkg(DD / NTC, (MTK + MT - 1) / MT);
    gemm_mma_kernel<<<gqg, 512, S_TOTAL>>>((__nv_bfloat16*)aqh_, (__nv_bfloat16*)aql_,
                                           wqh, wql, bwq, rq, nullptr, MTQ, 1);
    gemm_mma_kernel<<<gkg, 512, S_TOTAL>>>((__nv_bfloat16*)akh_, (__nv_bfloat16*)akl_,
                                           wkh, wkl, bwk, rk, nullptr, MTK, 1);
    // V GEMM epilogue fuses kv = relu(kp) * vp  (mult = rk, no relu)
    gemm_mma_kernel<<<gkg, 512, S_TOTAL>>>((__nv_bfloat16*)avh_, (__nv_bfloat16*)avl_,
                                           wvh, wvl, bwv, kv, rk, MTK, 0);

    kv_tilesum_kernel<<<dim3(NT, BB), 512>>>();
    tile_scan_kernel<<<BB, 512>>>();
    winout_kernel<<<dim3(NQT, BB), 512>>>((float*)d_out);
}

// round 9
// speedup vs baseline: 3.6570x; 1.2801x over previous
#include <cuda_runtime.h>
#include <cuda_fp16.h>
#include <cstdint>

// Problem constants (fixed by the dataset)
#define BB 4
#define LQ 4096
#define LK 5119
#define DD 512
#define CACHE_LEN 1024
#define EPSV 1e-5f

#define TSZ 64
#define NT ((LK + TSZ - 1) / TSZ)   // 80 tiles
#define NQT (LQ / TSZ)              // 64 output tiles

// GEMM tiling
#define MT 128           // M rows per CTA
#define NTC 256          // N cols per CTA
#define KCH 32           // K chunk (32 fp16 = 64 bytes per row)
#define NCH (DD / KCH)   // 16 chunks
#define NSTAGE 4

// smem per chunk-buffer: A_hi 8K | A_lo 8K | B 16K
#define SBUF   32768
#define OFF_AH 0
#define OFF_AL 8192
#define OFF_B  16384
#define S_TOTAL (NSTAGE * SBUF)   // 131072

// ---------------- scratch (__device__ globals) -----------------------------
__device__ float  g_rq[(size_t)BB * LQ * DD];        // relu(qp)
__device__ float  g_rk[(size_t)BB * LK * DD];        // relu(kp)
__device__ float  g_kv[(size_t)BB * LK * DD];        // relu(kp)*vp
__device__ float  g_tile[BB * NT * DD];              // tile prefix sums
__device__ __align__(256) __half g_wt[3 * DD * DD];  // [w][n][k] transposed fp16 W
// pre-normalized, fp16 hi/lo split A (row-major [m][k])
__device__ __align__(256) __half g_aqh[(size_t)BB * LQ * DD];
__device__ __align__(256) __half g_aql[(size_t)BB * LQ * DD];
__device__ __align__(256) __half g_akh[(size_t)BB * LK * DD];
__device__ __align__(256) __half g_akl[(size_t)BB * LK * DD];
__device__ __align__(256) __half g_avh[(size_t)BB * LK * DD];
__device__ __align__(256) __half g_avl[(size_t)BB * LK * DD];

// ================= helpers ================================================
__device__ __forceinline__ uint32_t smem_u32(const void* p) {
    uint32_t a;
    asm("{ .reg .u64 t; cvta.to.shared.u64 t, %1; cvt.u32.u64 %0, t; }" : "=r"(a) : "l"(p));
    return a;
}
__device__ __forceinline__ void cp16(uint32_t dst, const void* src) {
    asm volatile("cp.async.cg.shared.global [%0], [%1], 16;" :: "r"(dst), "l"(src));
}
__device__ __forceinline__ void cp_commit() {
    asm volatile("cp.async.commit_group;");
}
template <int N>
__device__ __forceinline__ void cp_wait() {
    asm volatile("cp.async.wait_group %0;" :: "n"(N));
}
__device__ __forceinline__ void ldsm4(uint32_t* r, uint32_t addr) {
    asm volatile("ldmatrix.sync.aligned.m8n8.x4.shared.b16 {%0,%1,%2,%3}, [%4];"
        : "=r"(r[0]), "=r"(r[1]), "=r"(r[2]), "=r"(r[3]) : "r"(addr));
}
__device__ __forceinline__ void mma16816(float* c, const uint32_t* a,
                                         uint32_t b0, uint32_t b1) {
    asm volatile(
        "mma.sync.aligned.m16n8k16.row.col.f32.f16.f16.f32 "
        "{%0,%1,%2,%3}, {%4,%5,%6,%7}, {%8,%9}, {%0,%1,%2,%3};"
        : "+f"(c[0]), "+f"(c[1]), "+f"(c[2]), "+f"(c[3])
        : "r"(a[0]), "r"(a[1]), "r"(a[2]), "r"(a[3]), "r"(b0), "r"(b1));
}
__device__ __forceinline__ uint32_t pack2h(__half a, __half b) {
    return (uint32_t)__half_as_ushort(a) | ((uint32_t)__half_as_ushort(b) << 16);
}

// ---------------- W prep: transpose + fp16 ---------------------------------
__global__ __launch_bounds__(256)
void wprep_kernel(const float* __restrict__ W0,
                  const float* __restrict__ W1,
                  const float* __restrict__ W2) {
    const float* W = (blockIdx.z == 0) ? W0 : (blockIdx.z == 1) ? W1 : W2;
    __shared__ float t[32][33];
    int n0 = blockIdx.x * 32, k0 = blockIdx.y * 32;
    int tx = threadIdx.x, ty = threadIdx.y;
    #pragma unroll
    for (int i = 0; i < 4; i++)
        t[ty + 8 * i][tx] = W[(size_t)(k0 + ty + 8 * i) * DD + n0 + tx];
    __syncthreads();
    __half* wt = g_wt + (size_t)blockIdx.z * DD * DD;
    #pragma unroll
    for (int i = 0; i < 4; i++) {
        int n = n0 + ty + 8 * i, k = k0 + tx;
        wt[(size_t)n * DD + k] = __float2half_rn(t[tx][ty + 8 * i]);
    }
}

// ---------------- fused LN + fp16 hi/lo split (warp per row) ---------------
__global__ __launch_bounds__(256)
void lnprep_kernel(const float* __restrict__ x,
                   const float* __restrict__ gam, const float* __restrict__ bet,
                   __half* __restrict__ hi, __half* __restrict__ lo,
                   int nrows) {
    int wid = threadIdx.x >> 5, lane = threadIdx.x & 31;
    int row = blockIdx.x * 8 + wid;
    if (row >= nrows) return;
    const float4* xr = reinterpret_cast<const float4*>(x + (size_t)row * DD);
    float4 v[4];
    float s = 0.f, s2 = 0.f;
    #pragma unroll
    for (int j = 0; j < 4; j++) {
        v[j] = xr[j * 32 + lane];
        s  += v[j].x + v[j].y + v[j].z + v[j].w;
        s2 += v[j].x * v[j].x + v[j].y * v[j].y + v[j].z * v[j].z + v[j].w * v[j].w;
    }
    #pragma unroll
    for (int o = 16; o > 0; o >>= 1) {
        s  += __shfl_xor_sync(0xffffffffu, s, o);
        s2 += __shfl_xor_sync(0xffffffffu, s2, o);
    }
    float m = s / (float)DD;
    float r = rsqrtf(s2 / (float)DD - m * m + EPSV);
    const float4* gr = reinterpret_cast<const float4*>(gam);
    const float4* br = reinterpret_cast<const float4*>(bet);
    uint2* hp = reinterpret_cast<uint2*>(hi + (size_t)row * DD);
    uint2* lp = reinterpret_cast<uint2*>(lo + (size_t)row * DD);
    #pragma unroll
    for (int j = 0; j < 4; j++) {
        float4 g4 = gr[j * 32 + lane];
        float4 b4 = br[j * 32 + lane];
        float y0 = (v[j].x - m) * r * g4.x + b4.x;
        float y1 = (v[j].y - m) * r * g4.y + b4.y;
        float y2 = (v[j].z - m) * r * g4.z + b4.z;
        float y3 = (v[j].w - m) * r * g4.w + b4.w;
        __half h0 = __float2half_rn(y0), h1 = __float2half_rn(y1);
        __half h2 = __float2half_rn(y2), h3 = __float2half_rn(y3);
        __half l0 = __float2half_rn(y0 - __half2float(h0));
        __half l1 = __float2half_rn(y1 - __half2float(h1));
        __half l2 = __float2half_rn(y2 - __half2float(h2));
        __half l3 = __float2half_rn(y3 - __half2float(h3));
        uint2 hv, lv;
        hv.x = pack2h(h0, h1); hv.y = pack2h(h2, h3);
        lv.x = pack2h(l0, l1); lv.y = pack2h(l2, l3);
        hp[j * 32 + lane] = hv;
        lp[j * 32 + lane] = lv;
    }
}

// ---------------- HMMA split-fp16 GEMM, 4-stage cp.async pipeline ----------
// C[m][n] = [relu]( A[m,:] @ Wt[n,:]^T + bw[n] ) [* mult[m,n]]
__global__ __launch_bounds__(512, 1)
void gemm_mma_kernel(const __half* __restrict__ Ah,
                     const __half* __restrict__ Al,
                     const __half* __restrict__ Wt,
                     const float* __restrict__ bw, float* __restrict__ C,
                     const float* __restrict__ mult,
                     int M, int do_relu) {
    extern __shared__ char smem[];
    const uint32_t su = smem_u32(smem);

    const int tid = threadIdx.x;
    const int wid = tid >> 5, lane = tid & 31;
    const int warpm = wid & 3, warpn = wid >> 2;   // 4 x 4 warps, warp tile 32x64
    const int g = lane >> 2, tig = lane & 3;
    const int bm = blockIdx.y * MT, bn = blockIdx.x * NTC;

    float acc[2][8][4];
    #pragma unroll
    for (int mi = 0; mi < 2; mi++)
        #pragma unroll
        for (int ni = 0; ni < 8; ni++)
            #pragma unroll
            for (int r = 0; r < 4; r++) acc[mi][ni][r] = 0.f;

    // ldmatrix per-lane source rows (64B rows, XOR swizzle on (row>>1)&3)
    const int arow = warpm * 32 + (lane & 7) + ((lane & 8) ? 8 : 0);
    const int acx  = (lane >> 4) & 1;              // k-col16 select
    const int axor = (arow >> 1) & 3;
    const int nrow = warpn * 64 + (lane & 7) + ((lane & 16) ? 8 : 0);
    const int ncx  = (lane >> 3) & 1;
    const int bxor = (nrow >> 1) & 3;

    #define ISSUE_CHUNK(kc_) do {                                              \
        int k0_ = (kc_) * KCH;                                                 \
        uint32_t db_ = su + ((kc_) & (NSTAGE - 1)) * SBUF;                     \
        {   /* A: 128 rows x 4 c16, one op per thread per split */             \
            int row = tid >> 2, c = tid & 3;                                   \
            int gm = bm + row; if (gm > M - 1) gm = M - 1;                     \
            uint32_t sw = (uint32_t)(row * 64 + ((c ^ ((row >> 1) & 3)) << 4));\
            cp16(db_ + OFF_AH + sw, Ah + (size_t)gm * DD + k0_ + c * 8);       \
            cp16(db_ + OFF_AL + sw, Al + (size_t)gm * DD + k0_ + c * 8);       \
        }                                                                      \
        _Pragma("unroll")                                                      \
        for (int it = 0; it < 2; it++) {   /* B: 256 rows x 4 c16 */           \
            int idx = tid + 512 * it;                                          \
            int n = idx >> 2, c = idx & 3;                                     \
            uint32_t sw = (uint32_t)(n * 64 + ((c ^ ((n >> 1) & 3)) << 4));    \
            cp16(db_ + OFF_B + sw, Wt + (size_t)(bn + n) * DD + k0_ + c * 8);  \
        }                                                                      \
        cp_commit();                                                           \
    } while (0)

    ISSUE_CHUNK(0);
    ISSUE_CHUNK(1);
    ISSUE_CHUNK(2);

    for (int kc = 0; kc < NCH; kc++) {
        if (kc + 3 < NCH)      { ISSUE_CHUNK(kc + 3); cp_wait<3>(); }
        else if (kc + 2 < NCH) cp_wait<2>();
        else if (kc + 1 < NCH) cp_wait<1>();
        else                   cp_wait<0>();
        __syncthreads();

        const uint32_t db = su + (kc & (NSTAGE - 1)) * SBUF;
        const uint32_t a_rowb = db + (uint32_t)(arow * 64);
        const uint32_t b_rowb = db + (uint32_t)(nrow * 64);

        #pragma unroll
        for (int ks = 0; ks < 2; ks++) {
            uint32_t ah[2][4], al[2][4];
            uint32_t a_sw = (uint32_t)(((ks * 2 + acx) ^ axor) << 4);
            #pragma unroll
            for (int mi = 0; mi < 2; mi++) {
                uint32_t base = a_rowb + (uint32_t)(mi * 16 * 64) + a_sw;
                ldsm4(ah[mi], base + OFF_AH);
                ldsm4(al[mi], base + OFF_AL);
            }
            uint32_t b_sw = (uint32_t)(((ks * 2 + ncx) ^ bxor) << 4);
            #pragma unroll
            for (int p = 0; p < 4; p++) {
                uint32_t bh[4];
                ldsm4(bh, b_rowb + (uint32_t)(p * 16 * 64) + b_sw + OFF_B);
                #pragma unroll
                for (int mi = 0; mi < 2; mi++) {
                    mma16816(acc[mi][2 * p],     ah[mi], bh[0], bh[1]);
                    mma16816(acc[mi][2 * p],     al[mi], bh[0], bh[1]);
                    mma16816(acc[mi][2 * p + 1], ah[mi], bh[2], bh[3]);
                    mma16816(acc[mi][2 * p + 1], al[mi], bh[2], bh[3]);
                }
            }
        }
        __syncthreads();
    }

    // ---------------- epilogue: bias [+relu] [*mult] -> gmem ---------------
    #pragma unroll
    for (int mi = 0; mi < 2; mi++) {
        int row0 = bm + warpm * 32 + mi * 16 + g;
        #pragma unroll
        for (int ni = 0; ni < 8; ni++) {
            int col = bn + warpn * 64 + ni * 8 + 2 * tig;
            float bw0 = bw[col], bw1 = bw[col + 1];
            float o0 = acc[mi][ni][0] + bw0;
            float o1 = acc[mi][ni][1] + bw1;
            float o2 = acc[mi][ni][2] + bw0;
            float o3 = acc[mi][ni][3] + bw1;
            if (do_relu) {
                o0 = fmaxf(o0, 0.f); o1 = fmaxf(o1, 0.f);
                o2 = fmaxf(o2, 0.f); o3 = fmaxf(o3, 0.f);
            }
            if (mult) {
                if (row0 < M) {
                    float2 m0 = *(const float2*)(mult + (size_t)row0 * DD + col);
                    o0 *= m0.x; o1 *= m0.y;
                }
                if (row0 + 8 < M) {
                    float2 m1 = *(const float2*)(mult + (size_t)(row0 + 8) * DD + col);
                    o2 *= m1.x; o3 *= m1.y;
                }
            }
            if (row0 < M)
                *(float2*)(C + (size_t)row0 * DD + col) = make_float2(o0, o1);
            if (row0 + 8 < M)
                *(float2*)(C + (size_t)(row0 + 8) * DD + col) = make_float2(o2, o3);
        }
    }
}

// ---------------- per-tile partial sums of kv ------------------------------
__global__ __launch_bounds__(512)
void kv_tilesum_kernel() {
    int t = blockIdx.x, b = blockIdx.y;
    int d = threadIdx.x;   // 512
    size_t base = ((size_t)b * LK) * DD + d;
    int l0 = t * TSZ;
    int lend = min(l0 + TSZ, LK);
    float s = 0.f;
    for (int l = l0; l < lend; l++)
        s += g_kv[base + (size_t)l * DD];
    g_tile[(b * NT + t) * DD + d] = s;
}

// ---------------- exclusive scan of tile sums (streaming) ------------------
__global__ __launch_bounds__(512)
void tile_scan_kernel() {
    int d = threadIdx.x;   // 512
    int b = blockIdx.x;
    float run = 0.f;
    for (int t = 0; t < NT; t++) {
        int idx = (b * NT + t) * DD + d;
        float v = g_tile[idx];
        g_tile[idx] = run;
        run += v;
    }
}

// ---------------- fused windowed-sum + relu(qp) multiply -> out ------------
// out[b,i,d] = rq[b,i,d] * (cs[i+1024] - cs[i]);  sup = 0 for these shapes
__global__ __launch_bounds__(512)
void winout_kernel(float* __restrict__ out) {
    int t = blockIdx.x, b = blockIdx.y;   // t in 0..NQT-1
    int d = threadIdx.x;                  // 512
    float run_lo = g_tile[(b * NT + t) * DD + d];
    float run_hi = g_tile[(b * NT + t + CACHE_LEN / TSZ) * DD + d];
    size_t kvb = ((size_t)b * LK) * DD + d;
    size_t qb  = ((size_t)b * LQ) * DD + d;
    #pragma unroll 4
    for (int r = 0; r < TSZ; r++) {
        int i = t * TSZ + r;
        float w = run_hi - run_lo;
        out[qb + (size_t)i * DD] = g_rq[qb + (size_t)i * DD] * w;
        run_lo += g_kv[kvb + (size_t)i * DD];
        int ihi = i + CACHE_LEN;
        if (ihi < LK) run_hi += g_kv[kvb + (size_t)ihi * DD];
    }
}

// ---------------------------------------------------------------------------
extern "C" void kernel_launch(void* const* d_in, const int* in_sizes, int n_in,
                              void* d_out, int out_size) {
    const float* q   = (const float*)d_in[0];
    const float* k   = (const float*)d_in[1];
    const float* v   = (const float*)d_in[2];
    const float* gq  = (const float*)d_in[3];
    const float* bq  = (const float*)d_in[4];
    const float* gk  = (const float*)d_in[5];
    const float* bk  = (const float*)d_in[6];
    const float* gv  = (const float*)d_in[7];
    const float* bv  = (const float*)d_in[8];
    const float* Wq  = (const float*)d_in[9];
    const float* bwq = (const float*)d_in[10];
    const float* Wk  = (const float*)d_in[11];
    const float* bwk = (const float*)d_in[12];
    const float* Wv  = (const float*)d_in[13];
    const float* bwv = (const float*)d_in[14];

    void *rq_, *rk_, *kv_, *wt_;
    void *aqh_, *aql_, *akh_, *akl_, *avh_, *avl_;
    cudaGetSymbolAddress(&rq_, g_rq);
    cudaGetSymbolAddress(&rk_, g_rk);
    cudaGetSymbolAddress(&kv_, g_kv);
    cudaGetSymbolAddress(&wt_, g_wt);
    cudaGetSymbolAddress(&aqh_, g_aqh);
    cudaGetSymbolAddress(&aql_, g_aql);
    cudaGetSymbolAddress(&akh_, g_akh);
    cudaGetSymbolAddress(&akl_, g_akl);
    cudaGetSymbolAddress(&avh_, g_avh);
    cudaGetSymbolAddress(&avl_, g_avl);
    float* rq = (float*)rq_;
    float* rk = (float*)rk_;
    float* kv = (float*)kv_;
    __half* wt = (__half*)wt_;

    cudaFuncSetAttribute(gemm_mma_kernel,
                         cudaFuncAttributeMaxDynamicSharedMemorySize, S_TOTAL);

    const int MTQ = BB * LQ;     // 16384
    const int MTK = BB * LK;     // 20476

    wprep_kernel<<<dim3(DD / 32, DD / 32, 3), dim3(32, 8)>>>(Wq, Wk, Wv);

    lnprep_kernel<<<(MTQ + 7) / 8, 256>>>(q, gq, bq, (__half*)aqh_, (__half*)aql_, MTQ);
    lnprep_kernel<<<(MTK + 7) / 8, 256>>>(k, gk, bk, (__half*)akh_, (__half*)akl_, MTK);
    lnprep_kernel<<<(MTK + 7) / 8, 256>>>(v, gv, bv, (__half*)avh_, (__half*)avl_, MTK);

    __half* wq16 = wt;
    __half* wk16 = wt + (size_t)DD * DD;
    __half* wv16 = wt + 2 * (size_t)DD * DD;

    dim3 gqg(DD / NTC, (MTQ + MT - 1) / MT);
    dim3 gkg(DD / NTC, (MTK + MT - 1) / MT);
    gemm_mma_kernel<<<gqg, 512, S_TOTAL>>>((__half*)aqh_, (__half*)aql_,
                                           wq16, bwq, rq, nullptr, MTQ, 1);
    gemm_mma_kernel<<<gkg, 512, S_TOTAL>>>((__half*)akh_, (__half*)akl_,
                                           wk16, bwk, rk, nullptr, MTK, 1);
    // V GEMM epilogue fuses kv = relu(kp) * vp  (mult = rk, no relu)
    gemm_mma_kernel<<<gkg, 512, S_TOTAL>>>((__half*)avh_, (__half*)avl_,
                                           wv16, bwv, kv, rk, MTK, 0);

    kv_tilesum_kernel<<<dim3(NT, BB), 512>>>();
    tile_scan_kernel<<<BB, 512>>>();
    winout_kernel<<<dim3(NQT, BB), 512>>>((float*)d_out);
}